// round 16
// baseline (speedup 1.0000x reference)
#include <cuda_runtime.h>
#include <cuda_fp16.h>
#include <cstdint>
#include <math.h>

#define B_  16
#define S_  1024
#define V_  512
#define E_  8
#define FF_ 2048
#define BV  (B_*V_)   // 8192 tokens (b,v)
#define BS  (B_*S_)   // 16384 rows (b,s)

// ================= device scratch (no allocation allowed) =================
__device__ __align__(16) __half g_xt_h [(size_t)BV * S_];      // MoE A (fp16) = x^T
__device__ __align__(16) float  g_part [2][(size_t)BV * S_];   // per-slot MoE outputs
__device__ __align__(16) float  g_x1   [(size_t)BS * V_];      // MoE+res fp32
__device__ __align__(16) __half g_x1_h [(size_t)BS * V_];      // fc1 A (fp16)
__device__ __align__(16) __half g_h_h  [(size_t)BS * FF_];     // fc2 A (fp16)
__device__ __align__(16) __half g_eW_h [(size_t)E_ * S_ * S_]; // MoE B (fp16)
__device__ __align__(16) __half g_f1W_h[(size_t)FF_ * V_];     // fc1 B
__device__ __align__(16) __half g_f2W_h[(size_t)V_ * FF_];     // fc2 B
__device__ int   g_tok [E_ * BV];
__device__ float g_w   [E_ * BV];
__device__ int   g_slot[E_ * BV];
__device__ int   g_cnt [E_];

__device__ __forceinline__ uint32_t smem_u32(const void* p) {
    uint32_t a;
    asm("{ .reg .u64 t; cvta.to.shared.u64 t, %1; cvt.u32.u64 %0, t; }" : "=r"(a) : "l"(p));
    return a;
}
#define LDSM4(r, a) \
    asm volatile("ldmatrix.sync.aligned.m8n8.x4.shared.b16 {%0,%1,%2,%3}, [%4];" \
                 : "=r"((r)[0]), "=r"((r)[1]), "=r"((r)[2]), "=r"((r)[3]) : "r"(a))
#define MMA16816(d, a, b0v, b1v) \
    asm volatile("mma.sync.aligned.m16n8k16.row.col.f32.f16.f16.f32 " \
                 "{%0,%1,%2,%3},{%4,%5,%6,%7},{%8,%9},{%0,%1,%2,%3};" \
                 : "+f"((d)[0]), "+f"((d)[1]), "+f"((d)[2]), "+f"((d)[3]) \
                 : "r"((a)[0]), "r"((a)[1]), "r"((a)[2]), "r"((a)[3]), "r"(b0v), "r"(b1v))
#define CP16(dst, src) \
    asm volatile("cp.async.cg.shared.global [%0], [%1], 16;" :: "r"(dst), "l"(src))
#define CP_COMMIT() asm volatile("cp.async.commit_group;" ::: "memory")
#define CP_WAIT0()  asm volatile("cp.async.wait_group 0;" ::: "memory")

// ================= small kernels =================
__global__ void zero_cnt_kernel() { if (threadIdx.x < E_) g_cnt[threadIdx.x] = 0; }

// fp32 -> fp16 cast, vectorized 4-wide
__global__ void cast_kernel(const float* __restrict__ in, __half* __restrict__ out,
                            size_t total4) {
    size_t i = (size_t)blockIdx.x * blockDim.x + threadIdx.x;
    size_t stride = (size_t)gridDim.x * blockDim.x;
    for (size_t idx = i; idx < total4; idx += stride) {
        float4 v = reinterpret_cast<const float4*>(in)[idx];
        reinterpret_cast<__half2*>(out)[idx * 2 + 0] = __floats2half2_rn(v.x, v.y);
        reinterpret_cast<__half2*>(out)[idx * 2 + 1] = __floats2half2_rn(v.z, v.w);
    }
}

// transpose x[B,S,V] -> g_xt_h fp16 only
__global__ void transpose_kernel(const float* __restrict__ x) {
    __shared__ float tile[32][33];
    int b = blockIdx.z;
    int s0 = blockIdx.x * 32, v0 = blockIdx.y * 32;
    int tx = threadIdx.x, ty = threadIdx.y;   // (32, 8)
    const float* xp = x + (size_t)b * S_ * V_;
    #pragma unroll
    for (int r = 0; r < 32; r += 8)
        tile[ty + r][tx] = xp[(size_t)(s0 + ty + r) * V_ + v0 + tx];
    __syncthreads();
    #pragma unroll
    for (int r = 0; r < 32; r += 8) {
        size_t o = ((size_t)b * V_ + v0 + ty + r) * S_ + s0 + tx;
        g_xt_h[o] = __float2half(tile[tx][ty + r]);
    }
}

// gating from x directly: block = (v-chunk of 32, batch b); fp32 math throughout
__global__ void __launch_bounds__(256) gating_kernel(const float* __restrict__ x,
                                                     const float* __restrict__ gate_W,
                                                     float* __restrict__ out_probs) {
    __shared__ float sgw[E_ * S_];         // 32 KB
    __shared__ float red[8][32][E_];       // 8 KB
    __shared__ float lsm[32][E_];
    const int tid = threadIdx.x;
    const int b = blockIdx.y, v0 = blockIdx.x * 32;
    for (int i = tid; i < E_ * S_; i += 256) sgw[i] = gate_W[i];
    __syncthreads();

    const int vl = tid & 31, sg = tid >> 5;   // warp sg handles rows s = sg, sg+8, ...
    float acc[E_] = {};
    const float* xp = x + (size_t)b * S_ * V_ + v0;
    for (int s = sg; s < S_; s += 8) {
        float xv = xp[(size_t)s * V_ + vl];   // 32 lanes: 128B coalesced
        #pragma unroll
        for (int e = 0; e < E_; e++) acc[e] = fmaf(xv, sgw[e * S_ + s], acc[e]);
    }
    #pragma unroll
    for (int e = 0; e < E_; e++) red[sg][vl][e] = acc[e];
    __syncthreads();
    {                                      // (v,e) pair per thread
        int v = tid >> 3, e = tid & 7;
        float s = 0.f;
        #pragma unroll
        for (int g = 0; g < 8; g++) s += red[g][v][e];
        lsm[v][e] = s;
    }
    __syncthreads();
    if (tid < 32) {
        int tok = b * V_ + v0 + tid;
        float m = lsm[tid][0];
        #pragma unroll
        for (int e = 1; e < E_; e++) m = fmaxf(m, lsm[tid][e]);
        float p[E_], sum = 0.f;
        #pragma unroll
        for (int e = 0; e < E_; e++) { p[e] = expf(lsm[tid][e] - m); sum += p[e]; }
        float inv = 1.f / sum;
        #pragma unroll
        for (int e = 0; e < E_; e++) { p[e] *= inv; out_probs[(size_t)tok * E_ + e] = p[e]; }
        int i0 = 0;
        #pragma unroll
        for (int e = 1; e < E_; e++) if (p[e] > p[i0]) i0 = e;
        int i1 = -1;
        #pragma unroll
        for (int e = 0; e < E_; e++) {
            if (e == i0) continue;
            if (i1 < 0 || p[e] > p[i1]) i1 = e;
        }
        int pos0 = atomicAdd(&g_cnt[i0], 1);
        g_tok[i0 * BV + pos0] = tok; g_w[i0 * BV + pos0] = p[i0]; g_slot[i0 * BV + pos0] = 0;
        int pos1 = atomicAdd(&g_cnt[i1], 1);
        g_tok[i1 * BV + pos1] = tok; g_w[i1 * BV + pos1] = p[i1]; g_slot[i1 * BV + pos1] = 1;
    }
}

// combine slots + relu + transpose back + residual -> g_x1 fp32 + g_x1_h fp16
__global__ void addres_kernel(const float* __restrict__ x) {
    __shared__ float tile[32][33];
    int b = blockIdx.z;
    int v0 = blockIdx.x * 32, s0 = blockIdx.y * 32;
    int tx = threadIdx.x, ty = threadIdx.y;
    #pragma unroll
    for (int r = 0; r < 32; r += 8) {
        size_t o = ((size_t)b * V_ + v0 + ty + r) * S_ + s0 + tx;
        tile[ty + r][tx] = g_part[0][o] + g_part[1][o];
    }
    __syncthreads();
    const float* xp = x + (size_t)b * S_ * V_;
    #pragma unroll
    for (int r = 0; r < 32; r += 8) {
        float tv = fmaxf(tile[tx][ty + r], 0.f);
        int s = s0 + ty + r, v = v0 + tx;
        size_t o = (size_t)s * V_ + v;
        float val = tv + xp[o];
        size_t bs = (size_t)b * S_ + s;
        g_x1[bs * V_ + v] = val;
        g_x1_h[bs * V_ + v] = __float2half(val);
    }
}

// ====== HMMA fp16 GEMM: 128x128 CTA tile, BK=64, 2-stage, interleaved cp.async ======
// MODE 0: MoE (gathered A rows, scaled scatter to g_part)
// MODE 1: fc1 (bias+relu -> g_h_h fp16)
// MODE 2: fc2 (bias+residual -> out fp32)
#define LDA 72                            // 144B row stride: ldmatrix conflict-free
#define AB_BYTES (128 * LDA * 2)          // 18432 per operand tile (128 x 64 halfs)
#define STAGE_BYTES (2 * AB_BYTES)        // 36864 per stage (A + B)
#define SMEM_DYN (2 * STAGE_BYTES)        // 73728

template<int MODE, int KDIM, int NDIM>
__global__ void __launch_bounds__(256, 2) mma_kernel(const __half* __restrict__ A,
                                                     const __half* __restrict__ Bm,
                                                     const float* __restrict__ bias,
                                                     float* __restrict__ out) {
    constexpr int NKT = KDIM / 64;
    extern __shared__ __align__(16) char smem[];
    __shared__ int   s_tok[128];
    __shared__ float s_w[128];
    __shared__ int   s_slot[128];

    const int tid = threadIdx.x;
    const int e = (MODE == 0) ? blockIdx.z : 0;
    const int m0 = blockIdx.y * 128;
    const int n0 = blockIdx.x * 128;
    int cnt;
    if (MODE == 0) { cnt = g_cnt[e]; if (m0 >= cnt) return; }
    else cnt = 1 << 30;

    const __half* Bp = (MODE == 0) ? (Bm + (size_t)e * S_ * KDIM) : Bm;
    const float* biasp = (MODE == 0) ? (bias + e * S_) : bias;

    if (MODE == 0) {
        if (tid < 128) {
            int gr = m0 + tid;
            if (gr < cnt) { s_tok[tid] = g_tok[e * BV + gr]; s_w[tid] = g_w[e * BV + gr];
                            s_slot[tid] = g_slot[e * BV + gr]; }
            else          { s_tok[tid] = 0; s_w[tid] = 0.f; s_slot[tid] = 0; }
        }
        __syncthreads();
    }

    // per-thread gmem chunk map: 4 chunks A + 4 chunks B (16B each) per stage.
    // tile = 128 rows x 64 halfs (128B = 8 chunks/row); 1024 chunks / 256 thr = 4.
    const __half* aptr[4];
    const __half* bptr[4];
    uint32_t abo[4];
    #pragma unroll
    for (int i = 0; i < 4; i++) {
        int c = tid + i * 256;
        int row = c >> 3, kc = c & 7;
        if (MODE == 0) aptr[i] = A + (size_t)s_tok[row] * KDIM + kc * 8;
        else           aptr[i] = A + (size_t)(m0 + row) * KDIM + kc * 8;
        bptr[i] = Bp + (size_t)(n0 + row) * KDIM + kc * 8;
        abo[i] = (uint32_t)(row * (LDA * 2) + kc * 16);   // 144B rows: 16B-aligned
    }

    const uint32_t sbase = smem_u32(smem);

    float acc[2][8][4];
    #pragma unroll
    for (int mi = 0; mi < 2; mi++)
        #pragma unroll
        for (int nf = 0; nf < 8; nf++)
            #pragma unroll
            for (int q = 0; q < 4; q++) acc[mi][nf][q] = 0.f;

    const int lane = tid & 31, wid = tid >> 5;
    const int wm = wid & 3, wn = wid >> 2;   // warp tile: rows wm*32, cols wn*64
    const int a_r = wm * 32 + (lane & 15);
    const int b_r = wn * 64 + (lane & 7) + ((lane >> 3) & 1) * 8;
    const int k_half = (lane >> 4) << 3;

    // prologue: stage 0
    {
        const uint32_t sa = sbase, sb = sbase + AB_BYTES;
        #pragma unroll
        for (int i = 0; i < 4; i++) CP16(sa + abo[i], aptr[i]);
        #pragma unroll
        for (int i = 0; i < 4; i++) CP16(sb + abo[i], bptr[i]);
        CP_COMMIT();
    }

    #pragma unroll 1
    for (int kt = 0; kt < NKT; kt++) {
        CP_WAIT0();            // stage kt landed (only outstanding group)
        __syncthreads();       // visible to all; other slot's reads drained
        const int cur = kt & 1;
        const uint32_t sAb = sbase + cur * STAGE_BYTES;
        const uint32_t sBb = sAb + AB_BYTES;
        const uint32_t sAn = sbase + (cur ^ 1) * STAGE_BYTES;
        const uint32_t sBn = sAn + AB_BYTES;
        const bool pref = (kt + 1 < NKT);
        const int koff = (kt + 1) * 64;

        #pragma unroll
        for (int kk = 0; kk < 4; kk++) {
            if (pref) {        // interleave next-stage issue under MMAs
                CP16(sAn + abo[kk], aptr[kk] + koff);
                CP16(sBn + abo[kk], bptr[kk] + koff);
            }
            const int k16 = kk * 16;
            uint32_t aF[2][4], bF[4][4];
            #pragma unroll
            for (int mi = 0; mi < 2; mi++) {
                uint32_t ad = sAb + ((a_r + mi * 16) * LDA + k16 + k_half) * 2;
                LDSM4(aF[mi], ad);
            }
            #pragma unroll
            for (int nq = 0; nq < 4; nq++) {
                uint32_t bd = sBb + ((b_r + nq * 16) * LDA + k16 + k_half) * 2;
                LDSM4(bF[nq], bd);
            }
            #pragma unroll
            for (int mi = 0; mi < 2; mi++)
                #pragma unroll
                for (int nq = 0; nq < 4; nq++) {
                    MMA16816(acc[mi][nq * 2 + 0], aF[mi], bF[nq][0], bF[nq][2]);
                    MMA16816(acc[mi][nq * 2 + 1], aF[mi], bF[nq][1], bF[nq][3]);
                }
        }
        if (pref) CP_COMMIT();
    }

    // ---- epilogue straight from C fragments ----
    const int g = lane >> 2, t = lane & 3;
    #pragma unroll
    for (int mi = 0; mi < 2; mi++) {
        #pragma unroll
        for (int nf = 0; nf < 8; nf++) {
            const int col = n0 + wn * 64 + nf * 8 + 2 * t;
            const float b0 = biasp[col], b1 = biasp[col + 1];
            #pragma unroll
            for (int h = 0; h < 2; h++) {   // h=0: row g, h=1: row g+8
                const int lr = wm * 32 + mi * 16 + g + h * 8;
                float v0 = acc[mi][nf][h * 2 + 0] + b0;
                float v1 = acc[mi][nf][h * 2 + 1] + b1;
                if (MODE == 0) {
                    if (m0 + lr < cnt) {
                        float wgt = s_w[lr];
                        float* dst = g_part[s_slot[lr]] + (size_t)s_tok[lr] * S_ + col;
                        *reinterpret_cast<float2*>(dst) = make_float2(wgt * v0, wgt * v1);
                    }
                } else if (MODE == 1) {
                    v0 = fmaxf(v0, 0.f); v1 = fmaxf(v1, 0.f);
                    size_t row = (size_t)(m0 + lr);
                    *reinterpret_cast<__half2*>(g_h_h + row * FF_ + col) =
                        __floats2half2_rn(v0, v1);
                } else {
                    size_t row = (size_t)(m0 + lr);
                    const float2 r2 = *reinterpret_cast<const float2*>(
                        g_x1 + row * NDIM + col);
                    *reinterpret_cast<float2*>(out + row * NDIM + col) =
                        make_float2(v0 + r2.x, v1 + r2.y);
                }
            }
        }
    }
}

// ================= launch =================
extern "C" void kernel_launch(void* const* d_in, const int* in_sizes, int n_in,
                              void* d_out, int out_size) {
    const float* x      = (const float*)d_in[0];
    const float* gate_W = (const float*)d_in[1];
    const float* exp_W  = (const float*)d_in[2];
    const float* exp_b  = (const float*)d_in[3];
    const float* fc1_W  = (const float*)d_in[4];
    const float* fc1_b  = (const float*)d_in[5];
    const float* fc2_W  = (const float*)d_in[6];
    const float* fc2_b  = (const float*)d_in[7];
    float* out       = (float*)d_out;
    float* out_probs = out + (size_t)B_ * S_ * V_;   // tuple: (x, probs)

    __half *p_xt_h, *p_eW, *p_f1W, *p_f2W, *p_x1_h, *p_h_h;
    cudaGetSymbolAddress((void**)&p_xt_h, g_xt_h);
    cudaGetSymbolAddress((void**)&p_eW,  g_eW_h);
    cudaGetSymbolAddress((void**)&p_f1W, g_f1W_h);
    cudaGetSymbolAddress((void**)&p_f2W, g_f2W_h);
    cudaGetSymbolAddress((void**)&p_x1_h, g_x1_h);
    cudaGetSymbolAddress((void**)&p_h_h,  g_h_h);

    cudaFuncSetAttribute(mma_kernel<0, S_, S_>,
                         cudaFuncAttributeMaxDynamicSharedMemorySize, SMEM_DYN);
    cudaFuncSetAttribute(mma_kernel<1, V_, FF_>,
                         cudaFuncAttributeMaxDynamicSharedMemorySize, SMEM_DYN);
    cudaFuncSetAttribute(mma_kernel<2, FF_, V_>,
                         cudaFuncAttributeMaxDynamicSharedMemorySize, SMEM_DYN);

    // host-side stream/event objects (lazy one-time creation; no device memory,
    // identical captured work every call)
    static cudaStream_t s1 = nullptr, s2 = nullptr;
    static cudaEvent_t evA = nullptr, evB = nullptr, evC = nullptr;
    if (s1 == nullptr) {
        cudaStreamCreateWithFlags(&s1, cudaStreamNonBlocking);
        cudaStreamCreateWithFlags(&s2, cudaStreamNonBlocking);
        cudaEventCreateWithFlags(&evA, cudaEventDisableTiming);
        cudaEventCreateWithFlags(&evB, cudaEventDisableTiming);
        cudaEventCreateWithFlags(&evC, cudaEventDisableTiming);
    }

    dim3 tb(32, 8);
    // main: counters; fork
    zero_cnt_kernel<<<1, 32>>>();
    cudaEventRecord(evA, 0);
    // s1: gating (needs zeroed counters)
    cudaStreamWaitEvent(s1, evA, 0);
    gating_kernel<<<dim3(V_ / 32, B_), 256, 0, s1>>>(x, gate_W, out_probs);
    cudaEventRecord(evB, s1);
    // s2: fc weight casts (needed only by fc1/fc2)
    cudaStreamWaitEvent(s2, evA, 0);
    cast_kernel<<<512, 256, 0, s2>>>(fc1_W, p_f1W, (size_t)FF_ * V_ / 4);
    cast_kernel<<<512, 256, 0, s2>>>(fc2_W, p_f2W, (size_t)V_ * FF_ / 4);
    cudaEventRecord(evC, s2);
    // main: expert-weight cast + x transpose (both feed mma<0>)
    cast_kernel<<<2048, 256>>>(exp_W, p_eW, (size_t)E_ * S_ * S_ / 4);
    transpose_kernel<<<dim3(S_ / 32, V_ / 32, B_), tb>>>(x);
    // join gating, run MoE
    cudaStreamWaitEvent(0, evB, 0);
    mma_kernel<0, S_, S_><<<dim3(S_ / 128, BV / 128, E_), 256, SMEM_DYN>>>(
        p_xt_h, p_eW, exp_b, nullptr);
    addres_kernel<<<dim3(V_ / 32, S_ / 32, B_), tb>>>(x);
    // join fc casts, run fc1/fc2
    cudaStreamWaitEvent(0, evC, 0);
    mma_kernel<1, V_, FF_><<<dim3(FF_ / 128, BS / 128, 1), 256, SMEM_DYN>>>(
        p_x1_h, p_f1W, fc1_b, nullptr);
    mma_kernel<2, FF_, V_><<<dim3(V_ / 128, BS / 128, 1), 256, SMEM_DYN>>>(
        p_h_h, p_f2W, fc2_b, out);
}

// round 17
// speedup vs baseline: 1.3093x; 1.3093x over previous
#include <cuda_runtime.h>
#include <cuda_fp16.h>
#include <cstdint>
#include <math.h>

#define B_  16
#define S_  1024
#define V_  512
#define E_  8
#define FF_ 2048
#define BV  (B_*V_)   // 8192 tokens (b,v)
#define BS  (B_*S_)   // 16384 rows (b,s)

// ================= device scratch (no allocation allowed) =================
__device__ __align__(16) __half g_xt_h [(size_t)BV * S_];      // MoE A (fp16) = x^T
__device__ __align__(16) float  g_part [2][(size_t)BV * S_];   // per-slot MoE outputs
__device__ __align__(16) float  g_x1   [(size_t)BS * V_];      // MoE+res fp32
__device__ __align__(16) __half g_x1_h [(size_t)BS * V_];      // fc1 A (fp16)
__device__ __align__(16) __half g_h_h  [(size_t)BS * FF_];     // fc2 A (fp16)
__device__ __align__(16) __half g_eW_h [(size_t)E_ * S_ * S_]; // MoE B (fp16)
__device__ __align__(16) __half g_f1W_h[(size_t)FF_ * V_];     // fc1 B
__device__ __align__(16) __half g_f2W_h[(size_t)V_ * FF_];     // fc2 B
__device__ int   g_tok [E_ * BV];
__device__ float g_w   [E_ * BV];
__device__ int   g_slot[E_ * BV];
__device__ int   g_cnt [E_];

__device__ __forceinline__ uint32_t smem_u32(const void* p) {
    uint32_t a;
    asm("{ .reg .u64 t; cvta.to.shared.u64 t, %1; cvt.u32.u64 %0, t; }" : "=r"(a) : "l"(p));
    return a;
}
#define LDSM4(r, a) \
    asm volatile("ldmatrix.sync.aligned.m8n8.x4.shared.b16 {%0,%1,%2,%3}, [%4];" \
                 : "=r"((r)[0]), "=r"((r)[1]), "=r"((r)[2]), "=r"((r)[3]) : "r"(a))
#define MMA16816(d, a, b0v, b1v) \
    asm volatile("mma.sync.aligned.m16n8k16.row.col.f32.f16.f16.f32 " \
                 "{%0,%1,%2,%3},{%4,%5,%6,%7},{%8,%9},{%0,%1,%2,%3};" \
                 : "+f"((d)[0]), "+f"((d)[1]), "+f"((d)[2]), "+f"((d)[3]) \
                 : "r"((a)[0]), "r"((a)[1]), "r"((a)[2]), "r"((a)[3]), "r"(b0v), "r"(b1v))
#define CP16(dst, src) \
    asm volatile("cp.async.cg.shared.global [%0], [%1], 16;" :: "r"(dst), "l"(src))
#define CP_COMMIT() asm volatile("cp.async.commit_group;" ::: "memory")
#define CP_WAIT0()  asm volatile("cp.async.wait_group 0;" ::: "memory")

// ================= small kernels =================
__global__ void zero_cnt_kernel() { if (threadIdx.x < E_) g_cnt[threadIdx.x] = 0; }

// fp32 -> fp16 cast, vectorized 4-wide
__global__ void cast_kernel(const float* __restrict__ in, __half* __restrict__ out,
                            size_t total4) {
    size_t i = (size_t)blockIdx.x * blockDim.x + threadIdx.x;
    size_t stride = (size_t)gridDim.x * blockDim.x;
    for (size_t idx = i; idx < total4; idx += stride) {
        float4 v = reinterpret_cast<const float4*>(in)[idx];
        reinterpret_cast<__half2*>(out)[idx * 2 + 0] = __floats2half2_rn(v.x, v.y);
        reinterpret_cast<__half2*>(out)[idx * 2 + 1] = __floats2half2_rn(v.z, v.w);
    }
}

// transpose x[B,S,V] -> g_xt_h fp16 only
__global__ void transpose_kernel(const float* __restrict__ x) {
    __shared__ float tile[32][33];
    int b = blockIdx.z;
    int s0 = blockIdx.x * 32, v0 = blockIdx.y * 32;
    int tx = threadIdx.x, ty = threadIdx.y;   // (32, 8)
    const float* xp = x + (size_t)b * S_ * V_;
    #pragma unroll
    for (int r = 0; r < 32; r += 8)
        tile[ty + r][tx] = xp[(size_t)(s0 + ty + r) * V_ + v0 + tx];
    __syncthreads();
    #pragma unroll
    for (int r = 0; r < 32; r += 8) {
        size_t o = ((size_t)b * V_ + v0 + ty + r) * S_ + s0 + tx;
        g_xt_h[o] = __float2half(tile[tx][ty + r]);
    }
}

// gating from x directly: block = (v-chunk of 32, batch b); fp32 math throughout
__global__ void __launch_bounds__(256) gating_kernel(const float* __restrict__ x,
                                                     const float* __restrict__ gate_W,
                                                     float* __restrict__ out_probs) {
    __shared__ float sgw[E_ * S_];         // 32 KB
    __shared__ float red[8][32][E_];       // 8 KB
    __shared__ float lsm[32][E_];
    const int tid = threadIdx.x;
    const int b = blockIdx.y, v0 = blockIdx.x * 32;
    for (int i = tid; i < E_ * S_; i += 256) sgw[i] = gate_W[i];
    __syncthreads();

    const int vl = tid & 31, sg = tid >> 5;   // warp sg handles rows s = sg, sg+8, ...
    float acc[E_] = {};
    const float* xp = x + (size_t)b * S_ * V_ + v0;
    for (int s = sg; s < S_; s += 8) {
        float xv = xp[(size_t)s * V_ + vl];   // 32 lanes: 128B coalesced
        #pragma unroll
        for (int e = 0; e < E_; e++) acc[e] = fmaf(xv, sgw[e * S_ + s], acc[e]);
    }
    #pragma unroll
    for (int e = 0; e < E_; e++) red[sg][vl][e] = acc[e];
    __syncthreads();
    {                                      // (v,e) pair per thread
        int v = tid >> 3, e = tid & 7;
        float s = 0.f;
        #pragma unroll
        for (int g = 0; g < 8; g++) s += red[g][v][e];
        lsm[v][e] = s;
    }
    __syncthreads();
    if (tid < 32) {
        int tok = b * V_ + v0 + tid;
        float m = lsm[tid][0];
        #pragma unroll
        for (int e = 1; e < E_; e++) m = fmaxf(m, lsm[tid][e]);
        float p[E_], sum = 0.f;
        #pragma unroll
        for (int e = 0; e < E_; e++) { p[e] = expf(lsm[tid][e] - m); sum += p[e]; }
        float inv = 1.f / sum;
        #pragma unroll
        for (int e = 0; e < E_; e++) { p[e] *= inv; out_probs[(size_t)tok * E_ + e] = p[e]; }
        int i0 = 0;
        #pragma unroll
        for (int e = 1; e < E_; e++) if (p[e] > p[i0]) i0 = e;
        int i1 = -1;
        #pragma unroll
        for (int e = 0; e < E_; e++) {
            if (e == i0) continue;
            if (i1 < 0 || p[e] > p[i1]) i1 = e;
        }
        int pos0 = atomicAdd(&g_cnt[i0], 1);
        g_tok[i0 * BV + pos0] = tok; g_w[i0 * BV + pos0] = p[i0]; g_slot[i0 * BV + pos0] = 0;
        int pos1 = atomicAdd(&g_cnt[i1], 1);
        g_tok[i1 * BV + pos1] = tok; g_w[i1 * BV + pos1] = p[i1]; g_slot[i1 * BV + pos1] = 1;
    }
}

// combine slots + relu + transpose back + residual -> g_x1 fp32 + g_x1_h fp16
__global__ void addres_kernel(const float* __restrict__ x) {
    __shared__ float tile[32][33];
    int b = blockIdx.z;
    int v0 = blockIdx.x * 32, s0 = blockIdx.y * 32;
    int tx = threadIdx.x, ty = threadIdx.y;
    #pragma unroll
    for (int r = 0; r < 32; r += 8) {
        size_t o = ((size_t)b * V_ + v0 + ty + r) * S_ + s0 + tx;
        tile[ty + r][tx] = g_part[0][o] + g_part[1][o];
    }
    __syncthreads();
    const float* xp = x + (size_t)b * S_ * V_;
    #pragma unroll
    for (int r = 0; r < 32; r += 8) {
        float tv = fmaxf(tile[tx][ty + r], 0.f);
        int s = s0 + ty + r, v = v0 + tx;
        size_t o = (size_t)s * V_ + v;
        float val = tv + xp[o];
        size_t bs = (size_t)b * S_ + s;
        g_x1[bs * V_ + v] = val;
        g_x1_h[bs * V_ + v] = __float2half(val);
    }
}

// ====== HMMA fp16 GEMM: 128x128 CTA tile, BK=64, 2-stage cp.async (R13 form) ======
// MODE 0: MoE (gathered A rows, scaled scatter to g_part)
// MODE 1: fc1 (bias+relu -> g_h_h fp16)
// MODE 2: fc2 (bias+residual -> out fp32)
#define LDA 72                            // 144B row stride: ldmatrix conflict-free
#define AB_BYTES (128 * LDA * 2)          // 18432 per operand tile (128 x 64 halfs)
#define STAGE_BYTES (2 * AB_BYTES)        // 36864 per stage (A + B)
#define SMEM_DYN (2 * STAGE_BYTES)        // 73728

template<int MODE, int KDIM, int NDIM>
__global__ void __launch_bounds__(256, 2) mma_kernel(const __half* __restrict__ A,
                                                     const __half* __restrict__ Bm,
                                                     const float* __restrict__ bias,
                                                     float* __restrict__ out) {
    constexpr int NKT = KDIM / 64;
    extern __shared__ __align__(16) char smem[];
    __shared__ int   s_tok[128];
    __shared__ float s_w[128];
    __shared__ int   s_slot[128];

    const int tid = threadIdx.x;
    const int e = (MODE == 0) ? blockIdx.z : 0;
    const int m0 = blockIdx.y * 128;
    const int n0 = blockIdx.x * 128;
    int cnt;
    if (MODE == 0) { cnt = g_cnt[e]; if (m0 >= cnt) return; }
    else cnt = 1 << 30;

    const __half* Bp = (MODE == 0) ? (Bm + (size_t)e * S_ * KDIM) : Bm;
    const float* biasp = (MODE == 0) ? (bias + e * S_) : bias;

    if (MODE == 0) {
        if (tid < 128) {
            int gr = m0 + tid;
            if (gr < cnt) { s_tok[tid] = g_tok[e * BV + gr]; s_w[tid] = g_w[e * BV + gr];
                            s_slot[tid] = g_slot[e * BV + gr]; }
            else          { s_tok[tid] = 0; s_w[tid] = 0.f; s_slot[tid] = 0; }
        }
        __syncthreads();
    }

    // per-thread gmem chunk map: 4 chunks A + 4 chunks B (16B each) per stage.
    const __half* aptr[4];
    const __half* bptr[4];
    uint32_t abo[4];
    #pragma unroll
    for (int i = 0; i < 4; i++) {
        int c = tid + i * 256;
        int row = c >> 3, kc = c & 7;
        if (MODE == 0) aptr[i] = A + (size_t)s_tok[row] * KDIM + kc * 8;
        else           aptr[i] = A + (size_t)(m0 + row) * KDIM + kc * 8;
        bptr[i] = Bp + (size_t)(n0 + row) * KDIM + kc * 8;
        abo[i] = (uint32_t)(row * (LDA * 2) + kc * 16);   // 144B rows: 16B-aligned
    }

    const uint32_t sbase = smem_u32(smem);
    auto issue_stage = [&](int kt, int slot) {
        const uint32_t sa = sbase + slot * STAGE_BYTES;
        const uint32_t sb = sa + AB_BYTES;
        const int koff = kt * 64;
        #pragma unroll
        for (int i = 0; i < 4; i++) CP16(sa + abo[i], aptr[i] + koff);
        #pragma unroll
        for (int i = 0; i < 4; i++) CP16(sb + abo[i], bptr[i] + koff);
    };

    float acc[2][8][4];
    #pragma unroll
    for (int mi = 0; mi < 2; mi++)
        #pragma unroll
        for (int nf = 0; nf < 8; nf++)
            #pragma unroll
            for (int q = 0; q < 4; q++) acc[mi][nf][q] = 0.f;

    const int lane = tid & 31, wid = tid >> 5;
    const int wm = wid & 3, wn = wid >> 2;   // warp tile: rows wm*32, cols wn*64
    const int a_r = wm * 32 + (lane & 15);
    const int b_r = wn * 64 + (lane & 7) + ((lane >> 3) & 1) * 8;
    const int k_half = (lane >> 4) << 3;

    issue_stage(0, 0); CP_COMMIT();

    #pragma unroll 1
    for (int kt = 0; kt < NKT; kt++) {
        CP_WAIT0();            // stage kt landed (only outstanding group)
        __syncthreads();       // visible to all; other slot's reads drained
        if (kt + 1 < NKT) { issue_stage(kt + 1, (kt + 1) & 1); CP_COMMIT(); }

        const uint32_t sAb = sbase + (kt & 1) * STAGE_BYTES;
        const uint32_t sBb = sAb + AB_BYTES;
        #pragma unroll
        for (int k16 = 0; k16 < 64; k16 += 16) {
            uint32_t aF[2][4], bF[4][4];
            #pragma unroll
            for (int mi = 0; mi < 2; mi++) {
                uint32_t ad = sAb + ((a_r + mi * 16) * LDA + k16 + k_half) * 2;
                LDSM4(aF[mi], ad);
            }
            #pragma unroll
            for (int nq = 0; nq < 4; nq++) {
                uint32_t bd = sBb + ((b_r + nq * 16) * LDA + k16 + k_half) * 2;
                LDSM4(bF[nq], bd);
            }
            #pragma unroll
            for (int mi = 0; mi < 2; mi++)
                #pragma unroll
                for (int nq = 0; nq < 4; nq++) {
                    MMA16816(acc[mi][nq * 2 + 0], aF[mi], bF[nq][0], bF[nq][2]);
                    MMA16816(acc[mi][nq * 2 + 1], aF[mi], bF[nq][1], bF[nq][3]);
                }
        }
    }

    // ---- epilogue straight from C fragments ----
    const int g = lane >> 2, t = lane & 3;
    #pragma unroll
    for (int mi = 0; mi < 2; mi++) {
        #pragma unroll
        for (int nf = 0; nf < 8; nf++) {
            const int col = n0 + wn * 64 + nf * 8 + 2 * t;
            const float b0 = biasp[col], b1 = biasp[col + 1];
            #pragma unroll
            for (int h = 0; h < 2; h++) {   // h=0: row g, h=1: row g+8
                const int lr = wm * 32 + mi * 16 + g + h * 8;
                float v0 = acc[mi][nf][h * 2 + 0] + b0;
                float v1 = acc[mi][nf][h * 2 + 1] + b1;
                if (MODE == 0) {
                    if (m0 + lr < cnt) {
                        float wgt = s_w[lr];
                        float* dst = g_part[s_slot[lr]] + (size_t)s_tok[lr] * S_ + col;
                        *reinterpret_cast<float2*>(dst) = make_float2(wgt * v0, wgt * v1);
                    }
                } else if (MODE == 1) {
                    v0 = fmaxf(v0, 0.f); v1 = fmaxf(v1, 0.f);
                    size_t row = (size_t)(m0 + lr);
                    *reinterpret_cast<__half2*>(g_h_h + row * FF_ + col) =
                        __floats2half2_rn(v0, v1);
                } else {
                    size_t row = (size_t)(m0 + lr);
                    const float2 r2 = *reinterpret_cast<const float2*>(
                        g_x1 + row * NDIM + col);
                    *reinterpret_cast<float2*>(out + row * NDIM + col) =
                        make_float2(v0 + r2.x, v1 + r2.y);
                }
            }
        }
    }
}

// ================= launch =================
extern "C" void kernel_launch(void* const* d_in, const int* in_sizes, int n_in,
                              void* d_out, int out_size) {
    const float* x      = (const float*)d_in[0];
    const float* gate_W = (const float*)d_in[1];
    const float* exp_W  = (const float*)d_in[2];
    const float* exp_b  = (const float*)d_in[3];
    const float* fc1_W  = (const float*)d_in[4];
    const float* fc1_b  = (const float*)d_in[5];
    const float* fc2_W  = (const float*)d_in[6];
    const float* fc2_b  = (const float*)d_in[7];
    float* out       = (float*)d_out;
    float* out_probs = out + (size_t)B_ * S_ * V_;   // tuple: (x, probs)

    __half *p_xt_h, *p_eW, *p_f1W, *p_f2W, *p_x1_h, *p_h_h;
    cudaGetSymbolAddress((void**)&p_xt_h, g_xt_h);
    cudaGetSymbolAddress((void**)&p_eW,  g_eW_h);
    cudaGetSymbolAddress((void**)&p_f1W, g_f1W_h);
    cudaGetSymbolAddress((void**)&p_f2W, g_f2W_h);
    cudaGetSymbolAddress((void**)&p_x1_h, g_x1_h);
    cudaGetSymbolAddress((void**)&p_h_h,  g_h_h);

    cudaFuncSetAttribute(mma_kernel<0, S_, S_>,
                         cudaFuncAttributeMaxDynamicSharedMemorySize, SMEM_DYN);
    cudaFuncSetAttribute(mma_kernel<1, V_, FF_>,
                         cudaFuncAttributeMaxDynamicSharedMemorySize, SMEM_DYN);
    cudaFuncSetAttribute(mma_kernel<2, FF_, V_>,
                         cudaFuncAttributeMaxDynamicSharedMemorySize, SMEM_DYN);

    // host-side stream/event objects (lazy one-time creation; no device memory,
    // identical captured work every call)
    static cudaStream_t s1 = nullptr, s2 = nullptr;
    static cudaEvent_t evA = nullptr, evB = nullptr, evC = nullptr;
    if (s1 == nullptr) {
        cudaStreamCreateWithFlags(&s1, cudaStreamNonBlocking);
        cudaStreamCreateWithFlags(&s2, cudaStreamNonBlocking);
        cudaEventCreateWithFlags(&evA, cudaEventDisableTiming);
        cudaEventCreateWithFlags(&evB, cudaEventDisableTiming);
        cudaEventCreateWithFlags(&evC, cudaEventDisableTiming);
    }

    dim3 tb(32, 8);
    // main: counters; fork
    zero_cnt_kernel<<<1, 32>>>();
    cudaEventRecord(evA, 0);
    // s1: gating (needs zeroed counters)
    cudaStreamWaitEvent(s1, evA, 0);
    gating_kernel<<<dim3(V_ / 32, B_), 256, 0, s1>>>(x, gate_W, out_probs);
    cudaEventRecord(evB, s1);
    // s2: fc weight casts (needed only by fc1/fc2)
    cudaStreamWaitEvent(s2, evA, 0);
    cast_kernel<<<512, 256, 0, s2>>>(fc1_W, p_f1W, (size_t)FF_ * V_ / 4);
    cast_kernel<<<512, 256, 0, s2>>>(fc2_W, p_f2W, (size_t)V_ * FF_ / 4);
    cudaEventRecord(evC, s2);
    // main: expert-weight cast + x transpose (both feed mma<0>)
    cast_kernel<<<2048, 256>>>(exp_W, p_eW, (size_t)E_ * S_ * S_ / 4);
    transpose_kernel<<<dim3(S_ / 32, V_ / 32, B_), tb>>>(x);
    // join gating, run MoE
    cudaStreamWaitEvent(0, evB, 0);
    mma_kernel<0, S_, S_><<<dim3(S_ / 128, BV / 128, E_), 256, SMEM_DYN>>>(
        p_xt_h, p_eW, exp_b, nullptr);
    addres_kernel<<<dim3(V_ / 32, S_ / 32, B_), tb>>>(x);
    // join fc casts, run fc1/fc2
    cudaStreamWaitEvent(0, evC, 0);
    mma_kernel<1, V_, FF_><<<dim3(FF_ / 128, BS / 128, 1), 256, SMEM_DYN>>>(
        p_x1_h, p_f1W, fc1_b, nullptr);
    mma_kernel<2, FF_, V_><<<dim3(V_ / 128, BS / 128, 1), 256, SMEM_DYN>>>(
        p_h_h, p_f2W, fc2_b, out);
}